// round 14
// baseline (speedup 1.0000x reference)
#include <cuda_runtime.h>
#include <cuda_bf16.h>
#include <cstdint>

#define NN 50000
#define NE 800000
#define DI 128
#define DH 128
#define DO 64
#define SPAD 132   // padded smem row stride (floats) for SIMT gemmB
#define NBLK 196   // (NN+255)/256

// ---- mma.sync gemm1 constants ----
#define KS2 136                        // bf16 smem row stride (272B)
#define OFF_AHI 0
#define OFF_ALO (128 * KS2 * 2)        // 34816
#define OFF_BHI (2 * 128 * KS2 * 2)    // 69632
#define OFF_BLO (3 * 128 * KS2 * 2)    // 104448
#define OFF_BIAS (4 * 128 * KS2 * 2)   // 139264
#define SM_MMA_TOTAL (OFF_BIAS + 512)  // 139776

// Scratch (device globals). 16B-aligned.
__device__ __align__(16) float g_agg[NN * DO];            // layer-2 mean (64d)
__device__ __align__(16) float g_h[NN * DH];              // layer-1 output
__device__ __align__(16) float g_p[NN * DO];              // h @ Wl2^T
__device__ __align__(16) __nv_bfloat16 g_xh[NN * DI];     // x hi
__device__ __align__(16) __nv_bfloat16 g_xl[NN * DI];     // x lo
__device__ __align__(16) __nv_bfloat16 g_mh[NN * DI];     // mean hi
__device__ __align__(16) __nv_bfloat16 g_ml[NN * DI];     // mean lo
__device__ __align__(16) __nv_bfloat16 g_wlh[DH * DI];    // Wl1 hi
__device__ __align__(16) __nv_bfloat16 g_wll[DH * DI];    // Wl1 lo
__device__ __align__(16) __nv_bfloat16 g_wrh[DH * DI];    // Wr1 hi
__device__ __align__(16) __nv_bfloat16 g_wrl[DH * DI];    // Wr1 lo
__device__ int g_rp[NN + 1];
__device__ int g_cur[NN];
__device__ int g_srt[NE];
__device__ int g_blksum[256];
__device__ int g_ei_is32;

// ---------------- helpers ----------------
__device__ __forceinline__ void fma2(unsigned long long &d, unsigned long long a, unsigned long long b) {
    asm("fma.rn.f32x2 %0, %1, %2, %0;" : "+l"(d) : "l"(a), "l"(b));
}
__device__ __forceinline__ float2 unpack2(unsigned long long v) {
    float2 r;
    asm("mov.b64 {%0, %1}, %2;" : "=f"(r.x), "=f"(r.y) : "l"(v));
    return r;
}
// split float4 -> bf16 hi/lo packed pairs
__device__ __forceinline__ void split4(float4 v, uint2& hp, uint2& lp) {
    __nv_bfloat16 h0 = __float2bfloat16(v.x), h1 = __float2bfloat16(v.y);
    __nv_bfloat16 h2 = __float2bfloat16(v.z), h3 = __float2bfloat16(v.w);
    __nv_bfloat16 l0 = __float2bfloat16(v.x - __bfloat162float(h0));
    __nv_bfloat16 l1 = __float2bfloat16(v.y - __bfloat162float(h1));
    __nv_bfloat16 l2 = __float2bfloat16(v.z - __bfloat162float(h2));
    __nv_bfloat16 l3 = __float2bfloat16(v.w - __bfloat162float(h3));
    hp.x = ((uint32_t)__bfloat16_as_ushort(h1) << 16) | __bfloat16_as_ushort(h0);
    hp.y = ((uint32_t)__bfloat16_as_ushort(h3) << 16) | __bfloat16_as_ushort(h2);
    lp.x = ((uint32_t)__bfloat16_as_ushort(l1) << 16) | __bfloat16_as_ushort(l0);
    lp.y = ((uint32_t)__bfloat16_as_ushort(l3) << 16) | __bfloat16_as_ushort(l2);
}

__device__ __forceinline__ void load_edge(const void* ei, int e, int is32, int& src, int& dst) {
    if (is32) {
        const int* p = (const int*)ei;
        src = p[e]; dst = p[NE + e];
    } else {
        const long long* p = (const long long*)ei;
        src = (int)p[e]; dst = (int)p[NE + e];
    }
}

// ---------------- init + CSR build ----------------
__global__ void k_init(const void* ei) {
    int i = blockIdx.x * blockDim.x + threadIdx.x;
    if (i < NN) g_cur[i] = 0;
    if (blockIdx.x == 0 && threadIdx.x == 0) {
        const long long* p = (const long long*)ei;
        int is32 = 0;
        for (int t = 0; t < 64; t++) {
            long long v = p[t];
            if (v < 0 || v >= NN) is32 = 1;
        }
        g_ei_is32 = is32;
    }
}
__global__ void k_hist(const void* __restrict__ ei) {
    int e = blockIdx.x * blockDim.x + threadIdx.x;
    if (e >= NE) return;
    int src, dst;
    load_edge(ei, e, g_ei_is32, src, dst);
    if ((unsigned)src < NN && (unsigned)dst < NN) atomicAdd(&g_cur[dst], 1);
}
__global__ void k_scan1() {
    __shared__ int s[256];
    int tid = threadIdx.x;
    int i = blockIdx.x * 256 + tid;
    s[tid] = (i < NN) ? g_cur[i] : 0;
    __syncthreads();
    for (int o = 128; o > 0; o >>= 1) {
        if (tid < o) s[tid] += s[tid + o];
        __syncthreads();
    }
    if (tid == 0) g_blksum[blockIdx.x] = s[0];
}
// merged scan2+scan3: each block scans the 196 block sums itself
__global__ void k_scan3m() {
    __shared__ int s[256], t[256];
    int tid = threadIdx.x;
    int i = blockIdx.x * 256 + tid;
    int v = (i < NN) ? g_cur[i] : 0;
    s[tid] = v;
    t[tid] = (tid < NBLK) ? g_blksum[tid] : 0;
    __syncthreads();
    for (int o = 1; o < 256; o <<= 1) {
        int a = (tid >= o) ? s[tid - o] : 0;
        int b = (tid >= o) ? t[tid - o] : 0;
        __syncthreads();
        s[tid] += a; t[tid] += b;
        __syncthreads();
    }
    int blkoff = (blockIdx.x == 0) ? 0 : t[blockIdx.x - 1];
    int excl = blkoff + s[tid] - v;
    if (i < NN) {
        g_rp[i]  = excl;
        g_cur[i] = excl;
        if (i == NN - 1) g_rp[NN] = excl + v;
    }
}
__global__ void k_reorder(const void* __restrict__ ei) {
    int e = blockIdx.x * blockDim.x + threadIdx.x;
    if (e >= NE) return;
    int src, dst;
    load_edge(ei, e, g_ei_is32, src, dst);
    if ((unsigned)src < NN && (unsigned)dst < NN) {
        int pos = atomicAdd(&g_cur[dst], 1);
        if (pos < NE) g_srt[pos] = src;
    }
}

// ---------------- conversions: x -> bf16 hi/lo; Wl1/Wr1 -> bf16 hi/lo ----------------
__global__ void k_conv(const float* __restrict__ x,
                       const float* __restrict__ Wl, const float* __restrict__ Wr) {
    int b = blockIdx.x;
    if (b < (NN * 32 + 255) / 256) {
        int idx  = b * 256 + threadIdx.x;
        int n    = idx >> 5;
        int lane = idx & 31;
        if (n < NN) {
            float4 v = *(const float4*)(x + (size_t)n * DI + lane * 4);
            uint2 hp, lp;
            split4(v, hp, lp);
            *(uint2*)(g_xh + (size_t)n * DI + lane * 4) = hp;
            *(uint2*)(g_xl + (size_t)n * DI + lane * 4) = lp;
        }
    } else {
        // weights: 2 matrices x 128 rows x 32 float4-chunks
        for (int i = threadIdx.x; i < 128 * 32; i += 256) {
            int row = i >> 5, lane = i & 31;
            uint2 hp, lp;
            float4 vl = *(const float4*)(Wl + row * DI + lane * 4);
            split4(vl, hp, lp);
            *(uint2*)(g_wlh + row * DI + lane * 4) = hp;
            *(uint2*)(g_wll + row * DI + lane * 4) = lp;
            float4 vr = *(const float4*)(Wr + row * DI + lane * 4);
            split4(vr, hp, lp);
            *(uint2*)(g_wrh + row * DI + lane * 4) = hp;
            *(uint2*)(g_wrl + row * DI + lane * 4) = lp;
        }
    }
}

// ---------------- gather (layer 1): mean of x[src] -> bf16 hi/lo ----------------
__global__ void k_gather_x(const float* __restrict__ x) {
    int n    = (blockIdx.x * blockDim.x + threadIdx.x) >> 5;
    int lane = threadIdx.x & 31;
    if (n >= NN) return;
    int beg = g_rp[n], end = g_rp[n + 1];
    float4 a = make_float4(0.f, 0.f, 0.f, 0.f);
    int i = beg;
    for (; i + 2 <= end; i += 2) {
        int s0 = g_srt[i], s1 = g_srt[i + 1];
        float4 v0 = *(const float4*)(x + (size_t)s0 * DI + lane * 4);
        float4 v1 = *(const float4*)(x + (size_t)s1 * DI + lane * 4);
        a.x += v0.x + v1.x; a.y += v0.y + v1.y;
        a.z += v0.z + v1.z; a.w += v0.w + v1.w;
    }
    if (i < end) {
        int s0 = g_srt[i];
        float4 v0 = *(const float4*)(x + (size_t)s0 * DI + lane * 4);
        a.x += v0.x; a.y += v0.y; a.z += v0.z; a.w += v0.w;
    }
    float inv = 1.0f / fmaxf((float)(end - beg), 1.0f);
    float4 m = make_float4(a.x * inv, a.y * inv, a.z * inv, a.w * inv);
    uint2 hp, lp;
    split4(m, hp, lp);
    *(uint2*)(g_mh + (size_t)n * DI + lane * 4) = hp;
    *(uint2*)(g_ml + (size_t)n * DI + lane * 4) = lp;
}

// ---------------- gather (layer 2): mean of g_p[src] per dst -> g_agg (64d) ----------------
__global__ void k_gather_p() {
    int n    = (blockIdx.x * blockDim.x + threadIdx.x) >> 5;
    int lane = threadIdx.x & 31;
    if (n >= NN) return;
    int beg = g_rp[n], end = g_rp[n + 1];
    float2 a = make_float2(0.f, 0.f);
    int i = beg;
    for (; i + 2 <= end; i += 2) {
        int s0 = g_srt[i], s1 = g_srt[i + 1];
        float2 v0 = *(const float2*)(g_p + (size_t)s0 * DO + lane * 2);
        float2 v1 = *(const float2*)(g_p + (size_t)s1 * DO + lane * 2);
        a.x += v0.x + v1.x; a.y += v0.y + v1.y;
    }
    if (i < end) {
        int s0 = g_srt[i];
        float2 v0 = *(const float2*)(g_p + (size_t)s0 * DO + lane * 2);
        a.x += v0.x; a.y += v0.y;
    }
    float inv = 1.0f / fmaxf((float)(end - beg), 1.0f);
    *(float2*)(g_agg + (size_t)n * DO + lane * 2) = make_float2(a.x * inv, a.y * inv);
}

// ================= mma.sync helpers =================
__device__ __forceinline__ uint32_t smem_u32(const void* p) {
    uint32_t a;
    asm("{ .reg .u64 t; cvta.to.shared.u64 t, %1; cvt.u32.u64 %0, t; }" : "=r"(a) : "l"(p));
    return a;
}
__device__ __forceinline__ void ldsm4(uint32_t& r0, uint32_t& r1, uint32_t& r2, uint32_t& r3,
                                      uint32_t addr) {
    asm volatile("ldmatrix.sync.aligned.m8n8.x4.shared.b16 {%0,%1,%2,%3}, [%4];"
                 : "=r"(r0), "=r"(r1), "=r"(r2), "=r"(r3) : "r"(addr));
}
__device__ __forceinline__ void mma_bf16(float* d, uint32_t a0, uint32_t a1, uint32_t a2,
                                         uint32_t a3, uint32_t b0, uint32_t b1) {
    asm volatile(
        "mma.sync.aligned.m16n8k16.row.col.f32.bf16.bf16.f32 "
        "{%0,%1,%2,%3}, {%4,%5,%6,%7}, {%8,%9}, {%0,%1,%2,%3};"
        : "+f"(d[0]), "+f"(d[1]), "+f"(d[2]), "+f"(d[3])
        : "r"(a0), "r"(a1), "r"(a2), "r"(a3), "r"(b0), "r"(b1));
}

// ---------------- layer-1 GEMM via mma.sync (split-bf16, pre-converted operands) ----------------
__global__ void __launch_bounds__(256, 1) k_gemm1_mma(const float* __restrict__ bl)
{
    extern __shared__ char smem[];
    const uint32_t sb = smem_u32(smem);
    const int tid  = threadIdx.x;
    const int warp = tid >> 5, lane = tid & 31;
    const int node0 = blockIdx.x * 128;

    if (tid < 128) ((float*)(smem + OFF_BIAS))[tid] = bl[tid];

    const int wm = (warp & 3) * 32;
    const int wn = (warp >> 2) * 64;

    float acc[2][8][4];
    #pragma unroll
    for (int mt = 0; mt < 2; mt++)
        #pragma unroll
        for (int nt = 0; nt < 8; nt++)
            #pragma unroll
            for (int q = 0; q < 4; q++) acc[mt][nt][q] = 0.f;

    const uint32_t aRow = (uint32_t)(lane & 15);
    const uint32_t aCol = (uint32_t)((lane >> 4) << 3);
    const uint32_t bRow = (uint32_t)(((lane >> 4) << 3) + (lane & 7));
    const uint32_t bCol = (uint32_t)(((lane >> 3) & 1) << 3);

    const int srow  = tid >> 1;
    const int scol0 = (tid & 1) * 64;
    const uint32_t sOff = (uint32_t)(srow * KS2 + scol0) * 2u;

    #pragma unroll
    for (int phase = 0; phase < 2; phase++) {
        // ---- copy-stage pre-converted bf16 tiles ----
        {
            int n = node0 + srow;
            bool valid = n < NN;
            const __nv_bfloat16* ah = ((phase == 0) ? g_mh : g_xh) + (size_t)n * DI + scol0;
            const __nv_bfloat16* al = ((phase == 0) ? g_ml : g_xl) + (size_t)n * DI + scol0;
            const __nv_bfloat16* bh = ((phase == 0) ? g_wlh : g_wrh) + srow * DI + scol0;
            const __nv_bfloat16* blo = ((phase == 0) ? g_wll : g_wrl) + srow * DI + scol0;
            uint4 z = make_uint4(0u, 0u, 0u, 0u);
            #pragma unroll
            for (int q = 0; q < 8; q++) {
                *(uint4*)(smem + OFF_AHI + sOff + 16u * q) = valid ? ((const uint4*)ah)[q] : z;
                *(uint4*)(smem + OFF_ALO + sOff + 16u * q) = valid ? ((const uint4*)al)[q] : z;
                *(uint4*)(smem + OFF_BHI + sOff + 16u * q) = ((const uint4*)bh)[q];
                *(uint4*)(smem + OFF_BLO + sOff + 16u * q) = ((const uint4*)blo)[q];
            }
        }
        __syncthreads();

        #pragma unroll
        for (int kb = 0; kb < DI; kb += 16) {
            uint32_t ah[2][4], al[2][4];
            #pragma unroll
            for (int mt = 0; mt < 2; mt++) {
                uint32_t eoff = ((uint32_t)(wm + mt * 16) + aRow) * KS2 + (uint32_t)kb + aCol;
                ldsm4(ah[mt][0], ah[mt][1], ah[mt][2], ah[mt][3], sb + OFF_AHI + eoff * 2u);
                ldsm4(al[mt][0], al[mt][1], al[mt][2], al[mt][3], sb + OFF_ALO + eoff * 2u);
            }
            #pragma unroll
            for (int np = 0; np < 4; np++) {
                uint32_t eoff = ((uint32_t)(wn + np * 16) + bRow) * KS2 + (uint32_t)kb + bCol;
                uint32_t bh[4], blq[4];
                ldsm4(bh[0], bh[1], bh[2], bh[3], sb + OFF_BHI + eoff * 2u);
                ldsm4(blq[0], blq[1], blq[2], blq[3], sb + OFF_BLO + eoff * 2u);
                #pragma unroll
                for (int mt = 0; mt < 2; mt++) {
                    mma_bf16(acc[mt][np*2],   ah[mt][0], ah[mt][1], ah[mt][2], ah[mt][3], bh[0],  bh[1]);
                    mma_bf16(acc[mt][np*2+1], ah[mt][0], ah[mt][1], ah[mt][2], ah[mt][3], bh[2],  bh[3]);
                    mma_bf16(acc[mt][np*2],   ah[mt][0], ah[mt][1], ah[mt][2], ah[mt][3], blq[0], blq[1]);
                    mma_bf16(acc[mt][np*2+1], ah[mt][0], ah[mt][1], ah[mt][2], ah[mt][3], blq[2], blq[3]);
                    mma_bf16(acc[mt][np*2],   al[mt][0], al[mt][1], al[mt][2], al[mt][3], bh[0],  bh[1]);
                    mma_bf16(acc[mt][np*2+1], al[mt][0], al[mt][1], al[mt][2], al[mt][3], bh[2],  bh[3]);
                }
            }
        }
        __syncthreads();
    }

    // ---- epilogue: bias + relu, direct stores ----
    const float* sBias = (const float*)(smem + OFF_BIAS);
    #pragma unroll
    for (int mt = 0; mt < 2; mt++) {
        #pragma unroll
        for (int nt = 0; nt < 8; nt++) {
            int gn = wn + nt * 8 + (lane & 3) * 2;
            float b0 = sBias[gn], b1 = sBias[gn + 1];
            int gm0 = node0 + wm + mt * 16 + (lane >> 2);
            if (gm0 < NN) {
                float2 v = make_float2(fmaxf(acc[mt][nt][0] + b0, 0.f),
                                       fmaxf(acc[mt][nt][1] + b1, 0.f));
                *(float2*)(g_h + (size_t)gm0 * DH + gn) = v;
            }
            int gm1 = gm0 + 8;
            if (gm1 < NN) {
                float2 v = make_float2(fmaxf(acc[mt][nt][2] + b0, 0.f),
                                       fmaxf(acc[mt][nt][3] + b1, 0.f));
                *(float2*)(g_h + (size_t)gm1 * DH + gn) = v;
            }
        }
    }
}

// ---------------- layer-2 GEMMs (SIMT, in=128, out=64) ----------------
template<bool FINAL>
__global__ void __launch_bounds__(256) k_gemmB(
    const float* __restrict__ W, const float* __restrict__ bias, float* __restrict__ out)
{
    extern __shared__ float smemf[];
    float* sW = smemf;
    float* sX = sW + DO * SPAD;

    const int tid   = threadIdx.x;
    const int node0 = blockIdx.x * 64;
    const int r     = tid >> 5;
    const int k4    = (tid & 31) * 4;

    #pragma unroll
    for (int it = 0; it < 8; it++) {
        int j = it * 8 + r;
        *(float4*)(sW + j * SPAD + k4) = *(const float4*)(W + j * DH + k4);
        int n = node0 + j;
        float4 h4 = make_float4(0.f, 0.f, 0.f, 0.f);
        if (n < NN) h4 = *(const float4*)(g_h + (size_t)n * DH + k4);
        *(float4*)(sX + j * SPAD + k4) = h4;
    }
    __syncthreads();

    const int lane = tid & 31;
    const int jl   = lane & 15;
    const int nb   = ((tid >> 5) * 2 + (lane >> 4)) * 4;

    unsigned long long acc[4][4];
    #pragma unroll
    for (int nn = 0; nn < 4; nn++)
        #pragma unroll
        for (int jj = 0; jj < 4; jj++) acc[nn][jj] = 0ull;

    #pragma unroll 4
    for (int k = 0; k < DH; k += 4) {
        ulonglong2 xv[4];
        #pragma unroll
        for (int nn = 0; nn < 4; nn++)
            xv[nn] = *(const ulonglong2*)(sX + (nb + nn) * SPAD + k);
        #pragma unroll
        for (int jj = 0; jj < 4; jj++) {
            int j = jl + 16 * jj;
            ulonglong2 wv = *(const ulonglong2*)(sW + j * SPAD + k);
            #pragma unroll
            for (int nn = 0; nn < 4; nn++) {
                fma2(acc[nn][jj], xv[nn].x, wv.x);
                fma2(acc[nn][jj], xv[nn].y, wv.y);
            }
        }
    }

    #pragma unroll
    for (int nn = 0; nn < 4; nn++) {
        int n = node0 + nb + nn;
        bool valid = (n < NN);
        if (FINAL) {
            float v[4];
            #pragma unroll
            for (int jj = 0; jj < 4; jj++) {
                int j = jl + 16 * jj;
                float2 s = unpack2(acc[nn][jj]);
                float t = s.x + s.y;
                if (valid) t += g_agg[(size_t)n * DO + j] + bias[j];
                v[jj] = valid ? fmaxf(t, 0.0f) : 0.0f;
            }
            float m = fmaxf(fmaxf(v[0], v[1]), fmaxf(v[2], v[3]));
            #pragma unroll
            for (int o = 8; o > 0; o >>= 1) m = fmaxf(m, __shfl_xor_sync(0xffffffffu, m, o));
            float ss = expf(v[0] - m) + expf(v[1] - m) + expf(v[2] - m) + expf(v[3] - m);
            #pragma unroll
            for (int o = 8; o > 0; o >>= 1) ss += __shfl_xor_sync(0xffffffffu, ss, o);
            float lse = m + logf(ss);
            if (valid) {
                #pragma unroll
                for (int jj = 0; jj < 4; jj++) {
                    int j = jl + 16 * jj;
                    out[(size_t)n * DO + j] = v[jj] - lse;
                }
            }
        } else {
            if (valid) {
                #pragma unroll
                for (int jj = 0; jj < 4; jj++) {
                    int j = jl + 16 * jj;
                    float2 s = unpack2(acc[nn][jj]);
                    g_p[(size_t)n * DO + j] = s.x + s.y;
                }
            }
        }
    }
}

// ---------------- launch ----------------
extern "C" void kernel_launch(void* const* d_in, const int* in_sizes, int n_in,
                              void* d_out, int out_size) {
    const float* x   = (const float*)d_in[0];
    const void*  ei  = d_in[1];
    const float* Wl1 = (const float*)d_in[2];
    const float* bl1 = (const float*)d_in[3];
    const float* Wr1 = (const float*)d_in[4];
    const float* Wl2 = (const float*)d_in[5];
    const float* bl2 = (const float*)d_in[6];
    const float* Wr2 = (const float*)d_in[7];
    float* out = (float*)d_out;

    const int SM2 = (2 * 64 * SPAD) * (int)sizeof(float);
    (void)cudaFuncSetAttribute(k_gemm1_mma,    cudaFuncAttributeMaxDynamicSharedMemorySize, SM_MMA_TOTAL);
    (void)cudaFuncSetAttribute(k_gemmB<false>, cudaFuncAttributeMaxDynamicSharedMemorySize, SM2);
    (void)cudaFuncSetAttribute(k_gemmB<true>,  cudaFuncAttributeMaxDynamicSharedMemorySize, SM2);

    const int GN = (NN + 63) / 64;
    const int GT = (NN + 127) / 128;
    const int EB = (NE + 255) / 256;
    const int GW = (NN * 32 + 255) / 256;   // 6250

    k_conv<<<GW + 1, 256>>>(x, Wl1, Wr1);
    k_init<<<NBLK, 256>>>(ei);
    k_hist<<<EB, 256>>>(ei);
    k_scan1<<<NBLK, 256>>>();
    k_scan3m<<<NBLK, 256>>>();
    k_reorder<<<EB, 256>>>(ei);
    k_gather_x<<<GW, 256>>>(x);
    k_gemm1_mma<<<GT, 256, SM_MMA_TOTAL>>>(bl1);
    k_gemmB<false><<<GN, 256, SM2>>>(Wl2, nullptr, nullptr);
    k_gather_p<<<GW, 256>>>();
    k_gemmB<true><<<GN, 256, SM2>>>(Wr2, bl2, out);
}

// round 16
// speedup vs baseline: 1.2546x; 1.2546x over previous
#include <cuda_runtime.h>
#include <cuda_bf16.h>
#include <cstdint>

#define NN 50000
#define NE 800000
#define DI 128
#define DH 128
#define DO 64
#define SPAD 132   // padded smem row stride (floats) for SIMT gemmB
#define NBLK 196   // (NN+255)/256

// ---- mma.sync gemm1 constants ----
#define KS2 136                        // bf16 smem row stride (272B)
#define OFF_AHI 0
#define OFF_ALO (128 * KS2 * 2)        // 34816
#define OFF_BHI (2 * 128 * KS2 * 2)    // 69632
#define OFF_BLO (3 * 128 * KS2 * 2)    // 104448
#define OFF_BIAS (4 * 128 * KS2 * 2)   // 139264
#define SM_MMA_TOTAL (OFF_BIAS + 512)  // 139776

// Scratch (device globals). 16B-aligned for float4 access.
__device__ __align__(16) float g_agg[NN * DI];   // mean features (l1: 128d; l2 reuse: first 64d)
__device__ __align__(16) float g_h[NN * DH];     // layer-1 output
__device__ __align__(16) float g_p[NN * DO];     // h @ Wl2^T
__device__ int g_rp[NN + 1];
__device__ int g_cur[NN];
__device__ int g_srt[NE];
__device__ int g_blksum[256];
__device__ int g_ei_is32;

// ---------------- helpers ----------------
__device__ __forceinline__ void fma2(unsigned long long &d, unsigned long long a, unsigned long long b) {
    asm("fma.rn.f32x2 %0, %1, %2, %0;" : "+l"(d) : "l"(a), "l"(b));
}
__device__ __forceinline__ float2 unpack2(unsigned long long v) {
    float2 r;
    asm("mov.b64 {%0, %1}, %2;" : "=f"(r.x), "=f"(r.y) : "l"(v));
    return r;
}

__device__ __forceinline__ void load_edge(const void* ei, int e, int is32, int& src, int& dst) {
    if (is32) {
        const int* p = (const int*)ei;
        src = p[e]; dst = p[NE + e];
    } else {
        const long long* p = (const long long*)ei;
        src = (int)p[e]; dst = (int)p[NE + e];
    }
}

// ---------------- init + CSR build ----------------
__global__ void k_init(const void* ei) {
    int i = blockIdx.x * blockDim.x + threadIdx.x;
    if (i < NN) g_cur[i] = 0;
    if (blockIdx.x == 0 && threadIdx.x == 0) {
        const long long* p = (const long long*)ei;
        int is32 = 0;
        for (int t = 0; t < 64; t++) {
            long long v = p[t];
            if (v < 0 || v >= NN) is32 = 1;
        }
        g_ei_is32 = is32;
    }
}
__global__ void k_hist(const void* __restrict__ ei) {
    int e = blockIdx.x * blockDim.x + threadIdx.x;
    if (e >= NE) return;
    int src, dst;
    load_edge(ei, e, g_ei_is32, src, dst);
    if ((unsigned)src < NN && (unsigned)dst < NN) atomicAdd(&g_cur[dst], 1);
}
__global__ void k_scan1() {
    __shared__ int s[256];
    int tid = threadIdx.x;
    int i = blockIdx.x * 256 + tid;
    s[tid] = (i < NN) ? g_cur[i] : 0;
    __syncthreads();
    for (int o = 128; o > 0; o >>= 1) {
        if (tid < o) s[tid] += s[tid + o];
        __syncthreads();
    }
    if (tid == 0) g_blksum[blockIdx.x] = s[0];
}
// merged scan2+scan3: each block scans the 196 block sums itself
__global__ void k_scan3m() {
    __shared__ int s[256], t[256];
    int tid = threadIdx.x;
    int i = blockIdx.x * 256 + tid;
    int v = (i < NN) ? g_cur[i] : 0;
    s[tid] = v;
    t[tid] = (tid < NBLK) ? g_blksum[tid] : 0;
    __syncthreads();
    for (int o = 1; o < 256; o <<= 1) {
        int a = (tid >= o) ? s[tid - o] : 0;
        int b = (tid >= o) ? t[tid - o] : 0;
        __syncthreads();
        s[tid] += a; t[tid] += b;
        __syncthreads();
    }
    int blkoff = (blockIdx.x == 0) ? 0 : t[blockIdx.x - 1];
    int excl = blkoff + s[tid] - v;
    if (i < NN) {
        g_rp[i]  = excl;
        g_cur[i] = excl;
        if (i == NN - 1) g_rp[NN] = excl + v;
    }
}
__global__ void k_reorder(const void* __restrict__ ei) {
    int e = blockIdx.x * blockDim.x + threadIdx.x;
    if (e >= NE) return;
    int src, dst;
    load_edge(ei, e, g_ei_is32, src, dst);
    if ((unsigned)src < NN && (unsigned)dst < NN) {
        int pos = atomicAdd(&g_cur[dst], 1);
        if (pos < NE) g_srt[pos] = src;
    }
}

// ---------------- gather (layer 1): mean of x[src] per dst -> g_agg ----------------
__global__ void k_gather_x(const float* __restrict__ x) {
    int n    = (blockIdx.x * blockDim.x + threadIdx.x) >> 5;
    int lane = threadIdx.x & 31;
    if (n >= NN) return;
    int beg = g_rp[n], end = g_rp[n + 1];
    float4 a = make_float4(0.f, 0.f, 0.f, 0.f);
    int i = beg;
    for (; i + 2 <= end; i += 2) {
        int s0 = g_srt[i], s1 = g_srt[i + 1];
        float4 v0 = *(const float4*)(x + (size_t)s0 * DI + lane * 4);
        float4 v1 = *(const float4*)(x + (size_t)s1 * DI + lane * 4);
        a.x += v0.x + v1.x; a.y += v0.y + v1.y;
        a.z += v0.z + v1.z; a.w += v0.w + v1.w;
    }
    if (i < end) {
        int s0 = g_srt[i];
        float4 v0 = *(const float4*)(x + (size_t)s0 * DI + lane * 4);
        a.x += v0.x; a.y += v0.y; a.z += v0.z; a.w += v0.w;
    }
    float inv = 1.0f / fmaxf((float)(end - beg), 1.0f);
    *(float4*)(g_agg + (size_t)n * DI + lane * 4) =
        make_float4(a.x * inv, a.y * inv, a.z * inv, a.w * inv);
}

// ---------------- gather (layer 2): mean of g_p[src] per dst -> g_agg (64d) ----------------
__global__ void k_gather_p() {
    int n    = (blockIdx.x * blockDim.x + threadIdx.x) >> 5;
    int lane = threadIdx.x & 31;
    if (n >= NN) return;
    int beg = g_rp[n], end = g_rp[n + 1];
    float2 a = make_float2(0.f, 0.f);
    int i = beg;
    for (; i + 2 <= end; i += 2) {
        int s0 = g_srt[i], s1 = g_srt[i + 1];
        float2 v0 = *(const float2*)(g_p + (size_t)s0 * DO + lane * 2);
        float2 v1 = *(const float2*)(g_p + (size_t)s1 * DO + lane * 2);
        a.x += v0.x + v1.x; a.y += v0.y + v1.y;
    }
    if (i < end) {
        int s0 = g_srt[i];
        float2 v0 = *(const float2*)(g_p + (size_t)s0 * DO + lane * 2);
        a.x += v0.x; a.y += v0.y;
    }
    float inv = 1.0f / fmaxf((float)(end - beg), 1.0f);
    *(float2*)(g_agg + (size_t)n * DO + lane * 2) = make_float2(a.x * inv, a.y * inv);
}

// ================= mma.sync helpers =================
__device__ __forceinline__ uint32_t smem_u32(const void* p) {
    uint32_t a;
    asm("{ .reg .u64 t; cvta.to.shared.u64 t, %1; cvt.u32.u64 %0, t; }" : "=r"(a) : "l"(p));
    return a;
}
__device__ __forceinline__ void ldsm4(uint32_t& r0, uint32_t& r1, uint32_t& r2, uint32_t& r3,
                                      uint32_t addr) {
    asm volatile("ldmatrix.sync.aligned.m8n8.x4.shared.b16 {%0,%1,%2,%3}, [%4];"
                 : "=r"(r0), "=r"(r1), "=r"(r2), "=r"(r3) : "r"(addr));
}
__device__ __forceinline__ void mma_bf16(float* d, uint32_t a0, uint32_t a1, uint32_t a2,
                                         uint32_t a3, uint32_t b0, uint32_t b1) {
    asm volatile(
        "mma.sync.aligned.m16n8k16.row.col.f32.bf16.bf16.f32 "
        "{%0,%1,%2,%3}, {%4,%5,%6,%7}, {%8,%9}, {%0,%1,%2,%3};"
        : "+f"(d[0]), "+f"(d[1]), "+f"(d[2]), "+f"(d[3])
        : "r"(a0), "r"(a1), "r"(a2), "r"(a3), "r"(b0), "r"(b1));
}
// coalesced tile stage: 128x128 fp32 tile (row-contiguous) -> bf16 hi/lo smem tiles.
// thread reads float4 at linear element e = (tid + 256*it)*4 -> fully coalesced 512B/warp.
__device__ __forceinline__ void stage_tile(const float* __restrict__ base,
                                           char* hi, char* lo,
                                           int tid, int rows_valid) {
    #pragma unroll
    for (int it = 0; it < 16; it++) {
        int e   = (tid + 256 * it) * 4;
        int row = e >> 7;
        int col = e & 127;
        bool valid = row < rows_valid;
        float4 v = valid ? *(const float4*)(base + e) : make_float4(0.f, 0.f, 0.f, 0.f);
        uint2 hp, lp;
        __nv_bfloat16 h0 = __float2bfloat16(v.x), h1 = __float2bfloat16(v.y);
        __nv_bfloat16 h2 = __float2bfloat16(v.z), h3 = __float2bfloat16(v.w);
        __nv_bfloat16 l0 = __float2bfloat16(v.x - __bfloat162float(h0));
        __nv_bfloat16 l1 = __float2bfloat16(v.y - __bfloat162float(h1));
        __nv_bfloat16 l2 = __float2bfloat16(v.z - __bfloat162float(h2));
        __nv_bfloat16 l3 = __float2bfloat16(v.w - __bfloat162float(h3));
        hp.x = ((uint32_t)__bfloat16_as_ushort(h1) << 16) | __bfloat16_as_ushort(h0);
        hp.y = ((uint32_t)__bfloat16_as_ushort(h3) << 16) | __bfloat16_as_ushort(h2);
        lp.x = ((uint32_t)__bfloat16_as_ushort(l1) << 16) | __bfloat16_as_ushort(l0);
        lp.y = ((uint32_t)__bfloat16_as_ushort(l3) << 16) | __bfloat16_as_ushort(l2);
        uint32_t soff = (uint32_t)(row * KS2 + col) * 2u;
        *(uint2*)(hi + soff) = hp;
        *(uint2*)(lo + soff) = lp;
    }
}

// ---------------- layer-1 GEMM via mma.sync (split-bf16, 3 products) ----------------
// h[128 nodes][128] = relu(mean @ Wl^T + x @ Wr^T + bl); 256 thr, warp tile 32x64.
__global__ void __launch_bounds__(256, 1) k_gemm1_mma(
    const float* __restrict__ x, const float* __restrict__ Wl,
    const float* __restrict__ bl, const float* __restrict__ Wr)
{
    extern __shared__ char smem[];
    const uint32_t sb = smem_u32(smem);
    const int tid  = threadIdx.x;
    const int warp = tid >> 5, lane = tid & 31;
    const int node0 = blockIdx.x * 128;

    if (tid < 128) ((float*)(smem + OFF_BIAS))[tid] = bl[tid];

    const int wm = (warp & 3) * 32;       // warp m-base (nodes)
    const int wn = (warp >> 2) * 64;      // warp n-base (outputs)

    float acc[2][8][4];
    #pragma unroll
    for (int mt = 0; mt < 2; mt++)
        #pragma unroll
        for (int nt = 0; nt < 8; nt++)
            #pragma unroll
            for (int q = 0; q < 4; q++) acc[mt][nt][q] = 0.f;

    const uint32_t aRow = (uint32_t)(lane & 15);
    const uint32_t aCol = (uint32_t)((lane >> 4) << 3);
    const uint32_t bRow = (uint32_t)(((lane >> 4) << 3) + (lane & 7));
    const uint32_t bCol = (uint32_t)(((lane >> 3) & 1) << 3);

    const int rows_valid = min(128, NN - node0);

    #pragma unroll
    for (int phase = 0; phase < 2; phase++) {
        // ---- stage A (nodes) and B (weights) as bf16 hi/lo, coalesced ----
        {
            const float* abase = ((phase == 0) ? g_agg : x) + (size_t)node0 * DI;
            const float* bbase = (phase == 0) ? Wl : Wr;
            stage_tile(abase, smem + OFF_AHI, smem + OFF_ALO, tid, rows_valid);
            stage_tile(bbase, smem + OFF_BHI, smem + OFF_BLO, tid, 128);
        }
        __syncthreads();

        #pragma unroll
        for (int kb = 0; kb < DI; kb += 16) {
            uint32_t ah[2][4], al[2][4];
            #pragma unroll
            for (int mt = 0; mt < 2; mt++) {
                uint32_t eoff = ((uint32_t)(wm + mt * 16) + aRow) * KS2 + (uint32_t)kb + aCol;
                ldsm4(ah[mt][0], ah[mt][1], ah[mt][2], ah[mt][3], sb + OFF_AHI + eoff * 2u);
                ldsm4(al[mt][0], al[mt][1], al[mt][2], al[mt][3], sb + OFF_ALO + eoff * 2u);
            }
            #pragma unroll
            for (int np = 0; np < 4; np++) {
                uint32_t eoff = ((uint32_t)(wn + np * 16) + bRow) * KS2 + (uint32_t)kb + bCol;
                uint32_t bh[4], blq[4];
                ldsm4(bh[0], bh[1], bh[2], bh[3], sb + OFF_BHI + eoff * 2u);
                ldsm4(blq[0], blq[1], blq[2], blq[3], sb + OFF_BLO + eoff * 2u);
                #pragma unroll
                for (int mt = 0; mt < 2; mt++) {
                    mma_bf16(acc[mt][np*2],   ah[mt][0], ah[mt][1], ah[mt][2], ah[mt][3], bh[0],  bh[1]);
                    mma_bf16(acc[mt][np*2+1], ah[mt][0], ah[mt][1], ah[mt][2], ah[mt][3], bh[2],  bh[3]);
                    mma_bf16(acc[mt][np*2],   ah[mt][0], ah[mt][1], ah[mt][2], ah[mt][3], blq[0], blq[1]);
                    mma_bf16(acc[mt][np*2+1], ah[mt][0], ah[mt][1], ah[mt][2], ah[mt][3], blq[2], blq[3]);
                    mma_bf16(acc[mt][np*2],   al[mt][0], al[mt][1], al[mt][2], al[mt][3], bh[0],  bh[1]);
                    mma_bf16(acc[mt][np*2+1], al[mt][0], al[mt][1], al[mt][2], al[mt][3], bh[2],  bh[3]);
                }
            }
        }
        __syncthreads();
    }

    // ---- epilogue: bias + relu, direct stores ----
    const float* sBias = (const float*)(smem + OFF_BIAS);
    #pragma unroll
    for (int mt = 0; mt < 2; mt++) {
        #pragma unroll
        for (int nt = 0; nt < 8; nt++) {
            int gn = wn + nt * 8 + (lane & 3) * 2;
            float b0 = sBias[gn], b1 = sBias[gn + 1];
            int gm0 = node0 + wm + mt * 16 + (lane >> 2);
            if (gm0 < NN) {
                float2 v = make_float2(fmaxf(acc[mt][nt][0] + b0, 0.f),
                                       fmaxf(acc[mt][nt][1] + b1, 0.f));
                *(float2*)(g_h + (size_t)gm0 * DH + gn) = v;
            }
            int gm1 = gm0 + 8;
            if (gm1 < NN) {
                float2 v = make_float2(fmaxf(acc[mt][nt][2] + b0, 0.f),
                                       fmaxf(acc[mt][nt][3] + b1, 0.f));
                *(float2*)(g_h + (size_t)gm1 * DH + gn) = v;
            }
        }
    }
}

// ---------------- layer-2 GEMMs (SIMT, in=128, out=64) ----------------
template<bool FINAL>
__global__ void __launch_bounds__(256) k_gemmB(
    const float* __restrict__ W, const float* __restrict__ bias, float* __restrict__ out)
{
    extern __shared__ float smemf[];
    float* sW = smemf;
    float* sX = sW + DO * SPAD;

    const int tid   = threadIdx.x;
    const int node0 = blockIdx.x * 64;
    const int r     = tid >> 5;
    const int k4    = (tid & 31) * 4;

    #pragma unroll
    for (int it = 0; it < 8; it++) {
        int j = it * 8 + r;
        *(float4*)(sW + j * SPAD + k4) = *(const float4*)(W + j * DH + k4);
        int n = node0 + j;
        float4 h4 = make_float4(0.f, 0.f, 0.f, 0.f);
        if (n < NN) h4 = *(const float4*)(g_h + (size_t)n * DH + k4);
        *(float4*)(sX + j * SPAD + k4) = h4;
    }
    __syncthreads();

    const int lane = tid & 31;
    const int jl   = lane & 15;
    const int nb   = ((tid >> 5) * 2 + (lane >> 4)) * 4;

    unsigned long long acc[4][4];
    #pragma unroll
    for (int nn = 0; nn < 4; nn++)
        #pragma unroll
        for (int jj = 0; jj < 4; jj++) acc[nn][jj] = 0ull;

    #pragma unroll 4
    for (int k = 0; k < DH; k += 4) {
        ulonglong2 xv[4];
        #pragma unroll
        for (int nn = 0; nn < 4; nn++)
            xv[nn] = *(const ulonglong2*)(sX + (nb + nn) * SPAD + k);
        #pragma unroll
        for (int jj = 0; jj < 4; jj++) {
            int j = jl + 16 * jj;
            ulonglong2 wv = *(const ulonglong2*)(sW + j * SPAD + k);
            #pragma unroll
            for (int nn = 0; nn < 4; nn++) {
                fma2(acc[nn][jj], xv[nn].x, wv.x);
                fma2(acc[nn][jj], xv[nn].y, wv.y);
            }
        }
    }

    #pragma unroll
    for (int nn = 0; nn < 4; nn++) {
        int n = node0 + nb + nn;
        bool valid = (n < NN);
        if (FINAL) {
            float v[4];
            #pragma unroll
            for (int jj = 0; jj < 4; jj++) {
                int j = jl + 16 * jj;
                float2 s = unpack2(acc[nn][jj]);
                float t = s.x + s.y;
                if (valid) t += g_agg[(size_t)n * DO + j] + bias[j];
                v[jj] = valid ? fmaxf(t, 0.0f) : 0.0f;
            }
            float m = fmaxf(fmaxf(v[0], v[1]), fmaxf(v[2], v[3]));
            #pragma unroll
            for (int o = 8; o > 0; o >>= 1) m = fmaxf(m, __shfl_xor_sync(0xffffffffu, m, o));
            float ss = expf(v[0] - m) + expf(v[1] - m) + expf(v[2] - m) + expf(v[3] - m);
            #pragma unroll
            for (int o = 8; o > 0; o >>= 1) ss += __shfl_xor_sync(0xffffffffu, ss, o);
            float lse = m + logf(ss);
            if (valid) {
                #pragma unroll
                for (int jj = 0; jj < 4; jj++) {
                    int j = jl + 16 * jj;
                    out[(size_t)n * DO + j] = v[jj] - lse;
                }
            }
        } else {
            if (valid) {
                #pragma unroll
                for (int jj = 0; jj < 4; jj++) {
                    int j = jl + 16 * jj;
                    float2 s = unpack2(acc[nn][jj]);
                    g_p[(size_t)n * DO + j] = s.x + s.y;
                }
            }
        }
    }
}

// ---------------- launch ----------------
extern "C" void kernel_launch(void* const* d_in, const int* in_sizes, int n_in,
                              void* d_out, int out_size) {
    const float* x   = (const float*)d_in[0];
    const void*  ei  = d_in[1];
    const float* Wl1 = (const float*)d_in[2];
    const float* bl1 = (const float*)d_in[3];
    const float* Wr1 = (const float*)d_in[4];
    const float* Wl2 = (const float*)d_in[5];
    const float* bl2 = (const float*)d_in[6];
    const float* Wr2 = (const float*)d_in[7];
    float* out = (float*)d_out;

    const int SM2 = (2 * 64 * SPAD) * (int)sizeof(float);
    (void)cudaFuncSetAttribute(k_gemm1_mma,    cudaFuncAttributeMaxDynamicSharedMemorySize, SM_MMA_TOTAL);
    (void)cudaFuncSetAttribute(k_gemmB<false>, cudaFuncAttributeMaxDynamicSharedMemorySize, SM2);
    (void)cudaFuncSetAttribute(k_gemmB<true>,  cudaFuncAttributeMaxDynamicSharedMemorySize, SM2);

    const int GN = (NN + 63) / 64;
    const int GT = (NN + 127) / 128;
    const int EB = (NE + 255) / 256;
    const int GW = (NN * 32 + 255) / 256;

    k_init<<<NBLK, 256>>>(ei);
    k_hist<<<EB, 256>>>(ei);
    k_scan1<<<NBLK, 256>>>();
    k_scan3m<<<NBLK, 256>>>();
    k_reorder<<<EB, 256>>>(ei);
    k_gather_x<<<GW, 256>>>(x);
    k_gemm1_mma<<<GT, 256, SM_MMA_TOTAL>>>(x, Wl1, bl1, Wr1);
    k_gemmB<false><<<GN, 256, SM2>>>(Wl2, nullptr, nullptr);
    k_gather_p<<<GW, 256>>>();
    k_gemmB<true><<<GN, 256, SM2>>>(Wr2, bl2, out);
}

// round 17
// speedup vs baseline: 1.3578x; 1.0822x over previous
#include <cuda_runtime.h>
#include <cuda_bf16.h>
#include <cstdint>

#define NN 50000
#define NE 800000
#define DI 128
#define DH 128
#define DO 64
#define SPAD 132   // padded smem row stride (floats) for SIMT gemmB
#define NBLK 196   // (NN+255)/256

// ---- mma.sync gemm1 constants ----
#define KS2 136                        // bf16 smem row stride (272B)
#define OFF_AHI 0
#define OFF_ALO (128 * KS2 * 2)        // 34816
#define OFF_BHI (2 * 128 * KS2 * 2)    // 69632
#define OFF_BLO (3 * 128 * KS2 * 2)    // 104448
#define OFF_BIAS (4 * 128 * KS2 * 2)   // 139264
#define SM_MMA_TOTAL (OFF_BIAS + 512)  // 139776

// Scratch (device globals). 16B-aligned for float4 access.
__device__ __align__(16) float g_agg[NN * DI];   // mean features (l1: 128d; l2 reuse: first 64d)
__device__ __align__(16) float g_h[NN * DH];     // layer-1 output
__device__ __align__(16) float g_p[NN * DO];     // h @ Wl2^T
__device__ int g_rp[NN + 1];
__device__ int g_cur[NN];
__device__ int g_srt[NE];
__device__ int g_blksum[256];
__device__ int g_ei_is32;

// ---------------- helpers ----------------
__device__ __forceinline__ void fma2(unsigned long long &d, unsigned long long a, unsigned long long b) {
    asm("fma.rn.f32x2 %0, %1, %2, %0;" : "+l"(d) : "l"(a), "l"(b));
}
__device__ __forceinline__ float2 unpack2(unsigned long long v) {
    float2 r;
    asm("mov.b64 {%0, %1}, %2;" : "=f"(r.x), "=f"(r.y) : "l"(v));
    return r;
}

__device__ __forceinline__ void load_edge(const void* ei, int e, int is32, int& src, int& dst) {
    if (is32) {
        const int* p = (const int*)ei;
        src = p[e]; dst = p[NE + e];
    } else {
        const long long* p = (const long long*)ei;
        src = (int)p[e]; dst = (int)p[NE + e];
    }
}

// ---------------- init + CSR build ----------------
__global__ void k_init(const void* ei) {
    int i = blockIdx.x * blockDim.x + threadIdx.x;
    if (i < NN) g_cur[i] = 0;
    if (blockIdx.x == 0 && threadIdx.x == 0) {
        const long long* p = (const long long*)ei;
        int is32 = 0;
        for (int t = 0; t < 64; t++) {
            long long v = p[t];
            if (v < 0 || v >= NN) is32 = 1;
        }
        g_ei_is32 = is32;
    }
}
__global__ void k_hist(const void* __restrict__ ei) {
    int e = blockIdx.x * blockDim.x + threadIdx.x;
    if (e >= NE) return;
    int src, dst;
    load_edge(ei, e, g_ei_is32, src, dst);
    if ((unsigned)src < NN && (unsigned)dst < NN) atomicAdd(&g_cur[dst], 1);
}
__global__ void k_scan1() {
    __shared__ int s[256];
    int tid = threadIdx.x;
    int i = blockIdx.x * 256 + tid;
    s[tid] = (i < NN) ? g_cur[i] : 0;
    __syncthreads();
    for (int o = 128; o > 0; o >>= 1) {
        if (tid < o) s[tid] += s[tid + o];
        __syncthreads();
    }
    if (tid == 0) g_blksum[blockIdx.x] = s[0];
}
// merged scan2+scan3: each block scans the 196 block sums itself
__global__ void k_scan3m() {
    __shared__ int s[256], t[256];
    int tid = threadIdx.x;
    int i = blockIdx.x * 256 + tid;
    int v = (i < NN) ? g_cur[i] : 0;
    s[tid] = v;
    t[tid] = (tid < NBLK) ? g_blksum[tid] : 0;
    __syncthreads();
    for (int o = 1; o < 256; o <<= 1) {
        int a = (tid >= o) ? s[tid - o] : 0;
        int b = (tid >= o) ? t[tid - o] : 0;
        __syncthreads();
        s[tid] += a; t[tid] += b;
        __syncthreads();
    }
    int blkoff = (blockIdx.x == 0) ? 0 : t[blockIdx.x - 1];
    int excl = blkoff + s[tid] - v;
    if (i < NN) {
        g_rp[i]  = excl;
        g_cur[i] = excl;
        if (i == NN - 1) g_rp[NN] = excl + v;
    }
}
__global__ void k_reorder(const void* __restrict__ ei) {
    int e = blockIdx.x * blockDim.x + threadIdx.x;
    if (e >= NE) return;
    int src, dst;
    load_edge(ei, e, g_ei_is32, src, dst);
    if ((unsigned)src < NN && (unsigned)dst < NN) {
        int pos = atomicAdd(&g_cur[dst], 1);
        if (pos < NE) g_srt[pos] = src;
    }
}

// ---------------- gather (layer 1): mean of x[src] per dst -> g_agg ----------------
__global__ void k_gather_x(const float* __restrict__ x) {
    int n    = (blockIdx.x * blockDim.x + threadIdx.x) >> 5;
    int lane = threadIdx.x & 31;
    if (n >= NN) return;
    int beg = g_rp[n], end = g_rp[n + 1];
    float4 a = make_float4(0.f, 0.f, 0.f, 0.f);
    int i = beg;
    for (; i + 2 <= end; i += 2) {
        int s0 = g_srt[i], s1 = g_srt[i + 1];
        float4 v0 = *(const float4*)(x + (size_t)s0 * DI + lane * 4);
        float4 v1 = *(const float4*)(x + (size_t)s1 * DI + lane * 4);
        a.x += v0.x + v1.x; a.y += v0.y + v1.y;
        a.z += v0.z + v1.z; a.w += v0.w + v1.w;
    }
    if (i < end) {
        int s0 = g_srt[i];
        float4 v0 = *(const float4*)(x + (size_t)s0 * DI + lane * 4);
        a.x += v0.x; a.y += v0.y; a.z += v0.z; a.w += v0.w;
    }
    float inv = 1.0f / fmaxf((float)(end - beg), 1.0f);
    *(float4*)(g_agg + (size_t)n * DI + lane * 4) =
        make_float4(a.x * inv, a.y * inv, a.z * inv, a.w * inv);
}

// ---------------- gather (layer 2): mean of g_p[src] per dst -> g_agg (64d) ----------------
__global__ void k_gather_p() {
    int n    = (blockIdx.x * blockDim.x + threadIdx.x) >> 5;
    int lane = threadIdx.x & 31;
    if (n >= NN) return;
    int beg = g_rp[n], end = g_rp[n + 1];
    float2 a = make_float2(0.f, 0.f);
    int i = beg;
    for (; i + 2 <= end; i += 2) {
        int s0 = g_srt[i], s1 = g_srt[i + 1];
        float2 v0 = *(const float2*)(g_p + (size_t)s0 * DO + lane * 2);
        float2 v1 = *(const float2*)(g_p + (size_t)s1 * DO + lane * 2);
        a.x += v0.x + v1.x; a.y += v0.y + v1.y;
    }
    if (i < end) {
        int s0 = g_srt[i];
        float2 v0 = *(const float2*)(g_p + (size_t)s0 * DO + lane * 2);
        a.x += v0.x; a.y += v0.y;
    }
    float inv = 1.0f / fmaxf((float)(end - beg), 1.0f);
    *(float2*)(g_agg + (size_t)n * DO + lane * 2) = make_float2(a.x * inv, a.y * inv);
}

// ================= mma.sync helpers =================
__device__ __forceinline__ uint32_t smem_u32(const void* p) {
    uint32_t a;
    asm("{ .reg .u64 t; cvta.to.shared.u64 t, %1; cvt.u32.u64 %0, t; }" : "=r"(a) : "l"(p));
    return a;
}
__device__ __forceinline__ void ldsm4(uint32_t& r0, uint32_t& r1, uint32_t& r2, uint32_t& r3,
                                      uint32_t addr) {
    asm volatile("ldmatrix.sync.aligned.m8n8.x4.shared.b16 {%0,%1,%2,%3}, [%4];"
                 : "=r"(r0), "=r"(r1), "=r"(r2), "=r"(r3) : "r"(addr));
}
__device__ __forceinline__ void mma_bf16(float* d, uint32_t a0, uint32_t a1, uint32_t a2,
                                         uint32_t a3, uint32_t b0, uint32_t b1) {
    asm volatile(
        "mma.sync.aligned.m16n8k16.row.col.f32.bf16.bf16.f32 "
        "{%0,%1,%2,%3}, {%4,%5,%6,%7}, {%8,%9}, {%0,%1,%2,%3};"
        : "+f"(d[0]), "+f"(d[1]), "+f"(d[2]), "+f"(d[3])
        : "r"(a0), "r"(a1), "r"(a2), "r"(a3), "r"(b0), "r"(b1));
}
// pack two floats as bf16 hi pair + lo pair
__device__ __forceinline__ void split2(float a, float b, uint32_t& hw, uint32_t& lw) {
    __nv_bfloat16 h0 = __float2bfloat16(a), h1 = __float2bfloat16(b);
    __nv_bfloat16 l0 = __float2bfloat16(a - __bfloat162float(h0));
    __nv_bfloat16 l1 = __float2bfloat16(b - __bfloat162float(h1));
    hw = ((uint32_t)__bfloat16_as_ushort(h1) << 16) | __bfloat16_as_ushort(h0);
    lw = ((uint32_t)__bfloat16_as_ushort(l1) << 16) | __bfloat16_as_ushort(l0);
}
// coalesced tile stage: rows x 128 fp32 tile (row-contiguous) -> bf16 hi/lo smem tiles.
__device__ __forceinline__ void stage_tile(const float* __restrict__ base,
                                           char* hi, char* lo,
                                           int tid, int rows_valid) {
    #pragma unroll
    for (int it = 0; it < 16; it++) {
        int e   = (tid + 256 * it) * 4;
        int row = e >> 7;
        int col = e & 127;
        bool valid = row < rows_valid;
        float4 v = valid ? *(const float4*)(base + e) : make_float4(0.f, 0.f, 0.f, 0.f);
        uint32_t h0, l0, h1, l1;
        split2(v.x, v.y, h0, l0);
        split2(v.z, v.w, h1, l1);
        uint32_t soff = (uint32_t)(row * KS2 + col) * 2u;
        *(uint2*)(hi + soff) = make_uint2(h0, h1);
        *(uint2*)(lo + soff) = make_uint2(l0, l1);
    }
}

// ---------------- layer-1 GEMM + fused p-GEMM via mma.sync (split-bf16) ----------------
// h[128 nodes][128] = relu(mean @ Wl^T + x @ Wr^T + bl); then p = h @ Wl2^T (fused).
__global__ void __launch_bounds__(256, 1) k_gemm1_mma(
    const float* __restrict__ x, const float* __restrict__ Wl,
    const float* __restrict__ bl, const float* __restrict__ Wr,
    const float* __restrict__ Wl2)
{
    extern __shared__ char smem[];
    const uint32_t sb = smem_u32(smem);
    const int tid  = threadIdx.x;
    const int warp = tid >> 5, lane = tid & 31;
    const int node0 = blockIdx.x * 128;

    if (tid < 128) ((float*)(smem + OFF_BIAS))[tid] = bl[tid];

    const int wm = (warp & 3) * 32;       // warp m-base (nodes)
    const int wn = (warp >> 2) * 64;      // warp n-base (outputs, layer-1)

    float acc[2][8][4];
    #pragma unroll
    for (int mt = 0; mt < 2; mt++)
        #pragma unroll
        for (int nt = 0; nt < 8; nt++)
            #pragma unroll
            for (int q = 0; q < 4; q++) acc[mt][nt][q] = 0.f;

    const uint32_t aRow = (uint32_t)(lane & 15);
    const uint32_t aCol = (uint32_t)((lane >> 4) << 3);
    const uint32_t bRow = (uint32_t)(((lane >> 4) << 3) + (lane & 7));
    const uint32_t bCol = (uint32_t)(((lane >> 3) & 1) << 3);

    const int rows_valid = min(128, NN - node0);

    #pragma unroll
    for (int phase = 0; phase < 2; phase++) {
        {
            const float* abase = ((phase == 0) ? g_agg : x) + (size_t)node0 * DI;
            const float* bbase = (phase == 0) ? Wl : Wr;
            stage_tile(abase, smem + OFF_AHI, smem + OFF_ALO, tid, rows_valid);
            stage_tile(bbase, smem + OFF_BHI, smem + OFF_BLO, tid, 128);
        }
        __syncthreads();

        #pragma unroll
        for (int kb = 0; kb < DI; kb += 16) {
            uint32_t ah[2][4], al[2][4];
            #pragma unroll
            for (int mt = 0; mt < 2; mt++) {
                uint32_t eoff = ((uint32_t)(wm + mt * 16) + aRow) * KS2 + (uint32_t)kb + aCol;
                ldsm4(ah[mt][0], ah[mt][1], ah[mt][2], ah[mt][3], sb + OFF_AHI + eoff * 2u);
                ldsm4(al[mt][0], al[mt][1], al[mt][2], al[mt][3], sb + OFF_ALO + eoff * 2u);
            }
            #pragma unroll
            for (int np = 0; np < 4; np++) {
                uint32_t eoff = ((uint32_t)(wn + np * 16) + bRow) * KS2 + (uint32_t)kb + bCol;
                uint32_t bh[4], blq[4];
                ldsm4(bh[0], bh[1], bh[2], bh[3], sb + OFF_BHI + eoff * 2u);
                ldsm4(blq[0], blq[1], blq[2], blq[3], sb + OFF_BLO + eoff * 2u);
                #pragma unroll
                for (int mt = 0; mt < 2; mt++) {
                    mma_bf16(acc[mt][np*2],   ah[mt][0], ah[mt][1], ah[mt][2], ah[mt][3], bh[0],  bh[1]);
                    mma_bf16(acc[mt][np*2+1], ah[mt][0], ah[mt][1], ah[mt][2], ah[mt][3], bh[2],  bh[3]);
                    mma_bf16(acc[mt][np*2],   ah[mt][0], ah[mt][1], ah[mt][2], ah[mt][3], blq[0], blq[1]);
                    mma_bf16(acc[mt][np*2+1], ah[mt][0], ah[mt][1], ah[mt][2], ah[mt][3], blq[2], blq[3]);
                    mma_bf16(acc[mt][np*2],   al[mt][0], al[mt][1], al[mt][2], al[mt][3], bh[0],  bh[1]);
                    mma_bf16(acc[mt][np*2+1], al[mt][0], al[mt][1], al[mt][2], al[mt][3], bh[2],  bh[3]);
                }
            }
        }
        __syncthreads();
    }

    // ---- epilogue 1: h = relu(acc + bias); store to g_h AND to smem A tiles (bf16 hi/lo) ----
    const float* sBias = (const float*)(smem + OFF_BIAS);
    #pragma unroll
    for (int mt = 0; mt < 2; mt++) {
        #pragma unroll
        for (int nt = 0; nt < 8; nt++) {
            int gn = wn + nt * 8 + (lane & 3) * 2;
            float b0 = sBias[gn], b1 = sBias[gn + 1];
            int lm0 = wm + mt * 16 + (lane >> 2);
            int lm1 = lm0 + 8;
            {
                float v0 = fmaxf(acc[mt][nt][0] + b0, 0.f);
                float v1 = fmaxf(acc[mt][nt][1] + b1, 0.f);
                if (node0 + lm0 < NN)
                    *(float2*)(g_h + (size_t)(node0 + lm0) * DH + gn) = make_float2(v0, v1);
                uint32_t hw, lw;
                split2(v0, v1, hw, lw);
                uint32_t soff = (uint32_t)(lm0 * KS2 + gn) * 2u;
                *(uint32_t*)(smem + OFF_AHI + soff) = hw;
                *(uint32_t*)(smem + OFF_ALO + soff) = lw;
            }
            {
                float v2 = fmaxf(acc[mt][nt][2] + b0, 0.f);
                float v3 = fmaxf(acc[mt][nt][3] + b1, 0.f);
                if (node0 + lm1 < NN)
                    *(float2*)(g_h + (size_t)(node0 + lm1) * DH + gn) = make_float2(v2, v3);
                uint32_t hw, lw;
                split2(v2, v3, hw, lw);
                uint32_t soff = (uint32_t)(lm1 * KS2 + gn) * 2u;
                *(uint32_t*)(smem + OFF_AHI + soff) = hw;
                *(uint32_t*)(smem + OFF_ALO + soff) = lw;
            }
        }
    }
    // stage Wl2 (64 rows x 128) into B tiles
    stage_tile(Wl2, smem + OFF_BHI, smem + OFF_BLO, tid, 64);
    __syncthreads();

    // ---- fused p-GEMM: p[128 x 64] = h @ Wl2^T ----
    const int wn2 = (warp >> 2) * 32;     // warp n-base (layer-2 outputs)
    float acc2[2][4][4];
    #pragma unroll
    for (int mt = 0; mt < 2; mt++)
        #pragma unroll
        for (int nt = 0; nt < 4; nt++)
            #pragma unroll
            for (int q = 0; q < 4; q++) acc2[mt][nt][q] = 0.f;

    #pragma unroll
    for (int kb = 0; kb < DH; kb += 16) {
        uint32_t ah[2][4], al[2][4];
        #pragma unroll
        for (int mt = 0; mt < 2; mt++) {
            uint32_t eoff = ((uint32_t)(wm + mt * 16) + aRow) * KS2 + (uint32_t)kb + aCol;
            ldsm4(ah[mt][0], ah[mt][1], ah[mt][2], ah[mt][3], sb + OFF_AHI + eoff * 2u);
            ldsm4(al[mt][0], al[mt][1], al[mt][2], al[mt][3], sb + OFF_ALO + eoff * 2u);
        }
        #pragma unroll
        for (int np = 0; np < 2; np++) {
            uint32_t eoff = ((uint32_t)(wn2 + np * 16) + bRow) * KS2 + (uint32_t)kb + bCol;
            uint32_t bh[4], blq[4];
            ldsm4(bh[0], bh[1], bh[2], bh[3], sb + OFF_BHI + eoff * 2u);
            ldsm4(blq[0], blq[1], blq[2], blq[3], sb + OFF_BLO + eoff * 2u);
            #pragma unroll
            for (int mt = 0; mt < 2; mt++) {
                mma_bf16(acc2[mt][np*2],   ah[mt][0], ah[mt][1], ah[mt][2], ah[mt][3], bh[0],  bh[1]);
                mma_bf16(acc2[mt][np*2+1], ah[mt][0], ah[mt][1], ah[mt][2], ah[mt][3], bh[2],  bh[3]);
                mma_bf16(acc2[mt][np*2],   ah[mt][0], ah[mt][1], ah[mt][2], ah[mt][3], blq[0], blq[1]);
                mma_bf16(acc2[mt][np*2+1], ah[mt][0], ah[mt][1], ah[mt][2], ah[mt][3], blq[2], blq[3]);
                mma_bf16(acc2[mt][np*2],   al[mt][0], al[mt][1], al[mt][2], al[mt][3], bh[0],  bh[1]);
                mma_bf16(acc2[mt][np*2+1], al[mt][0], al[mt][1], al[mt][2], al[mt][3], bh[2],  bh[3]);
            }
        }
    }

    // ---- epilogue 2: store p ----
    #pragma unroll
    for (int mt = 0; mt < 2; mt++) {
        #pragma unroll
        for (int nt = 0; nt < 4; nt++) {
            int gn = wn2 + nt * 8 + (lane & 3) * 2;
            int gm0 = node0 + wm + mt * 16 + (lane >> 2);
            if (gm0 < NN)
                *(float2*)(g_p + (size_t)gm0 * DO + gn) =
                    make_float2(acc2[mt][nt][0], acc2[mt][nt][1]);
            int gm1 = gm0 + 8;
            if (gm1 < NN)
                *(float2*)(g_p + (size_t)gm1 * DO + gn) =
                    make_float2(acc2[mt][nt][2], acc2[mt][nt][3]);
        }
    }
}

// ---------------- final layer-2 GEMM (SIMT): out = lsm(relu(mean + bl2 + h @ Wr2^T)) ----------------
__global__ void __launch_bounds__(256) k_gemmF(
    const float* __restrict__ W, const float* __restrict__ bias, float* __restrict__ out)
{
    extern __shared__ float smemf[];
    float* sW = smemf;
    float* sX = sW + DO * SPAD;

    const int tid   = threadIdx.x;
    const int node0 = blockIdx.x * 64;
    const int r     = tid >> 5;
    const int k4    = (tid & 31) * 4;

    #pragma unroll
    for (int it = 0; it < 8; it++) {
        int j = it * 8 + r;
        *(float4*)(sW + j * SPAD + k4) = *(const float4*)(W + j * DH + k4);
        int n = node0 + j;
        float4 h4 = make_float4(0.f, 0.f, 0.f, 0.f);
        if (n < NN) h4 = *(const float4*)(g_h + (size_t)n * DH + k4);
        *(float4*)(sX + j * SPAD + k4) = h4;
    }
    __syncthreads();

    const int lane = tid & 31;
    const int jl   = lane & 15;
    const int nb   = ((tid >> 5) * 2 + (lane >> 4)) * 4;

    unsigned long long acc[4][4];
    #pragma unroll
    for (int nn = 0; nn < 4; nn++)
        #pragma unroll
        for (int jj = 0; jj < 4; jj++) acc[nn][jj] = 0ull;

    #pragma unroll 4
    for (int k = 0; k < DH; k += 4) {
        ulonglong2 xv[4];
        #pragma unroll
        for (int nn = 0; nn < 4; nn++)
            xv[nn] = *(const ulonglong2*)(sX + (nb + nn) * SPAD + k);
        #pragma unroll
        for (int jj = 0; jj < 4; jj++) {
            int j = jl + 16 * jj;
            ulonglong2 wv = *(const ulonglong2*)(sW + j * SPAD + k);
            #pragma unroll
            for (int nn = 0; nn < 4; nn++) {
                fma2(acc[nn][jj], xv[nn].x, wv.x);
                fma2(acc[nn][jj], xv[nn].y, wv.y);
            }
        }
    }

    #pragma unroll
    for (int nn = 0; nn < 4; nn++) {
        int n = node0 + nb + nn;
        bool valid = (n < NN);
        float v[4];
        #pragma unroll
        for (int jj = 0; jj < 4; jj++) {
            int j = jl + 16 * jj;
            float2 s = unpack2(acc[nn][jj]);
            float t = s.x + s.y;
            if (valid) t += g_agg[(size_t)n * DO + j] + bias[j];
            v[jj] = valid ? fmaxf(t, 0.0f) : 0.0f;
        }
        float m = fmaxf(fmaxf(v[0], v[1]), fmaxf(v[2], v[3]));
        #pragma unroll
        for (int o = 8; o > 0; o >>= 1) m = fmaxf(m, __shfl_xor_sync(0xffffffffu, m, o));
        float ss = expf(v[0] - m) + expf(v[1] - m) + expf(v[2] - m) + expf(v[3] - m);
        #pragma unroll
        for (int o = 8; o > 0; o >>= 1) ss += __shfl_xor_sync(0xffffffffu, ss, o);
        float lse = m + logf(ss);
        if (valid) {
            #pragma unroll
            for (int jj = 0; jj < 4; jj++) {
                int j = jl + 16 * jj;
                out[(size_t)n * DO + j] = v[jj] - lse;
            }
        }
    }
}

// ---------------- launch ----------------
extern "C" void kernel_launch(void* const* d_in, const int* in_sizes, int n_in,
                              void* d_out, int out_size) {
    const float* x   = (const float*)d_in[0];
    const void*  ei  = d_in[1];
    const float* Wl1 = (const float*)d_in[2];
    const float* bl1 = (const float*)d_in[3];
    const float* Wr1 = (const float*)d_in[4];
    const float* Wl2 = (const float*)d_in[5];
    const float* bl2 = (const float*)d_in[6];
    const float* Wr2 = (const float*)d_in[7];
    float* out = (float*)d_out;

    const int SM2 = (2 * 64 * SPAD) * (int)sizeof(float);
    (void)cudaFuncSetAttribute(k_gemm1_mma, cudaFuncAttributeMaxDynamicSharedMemorySize, SM_MMA_TOTAL);
    (void)cudaFuncSetAttribute(k_gemmF,     cudaFuncAttributeMaxDynamicSharedMemorySize, SM2);

    const int GN = (NN + 63) / 64;
    const int GT = (NN + 127) / 128;
    const int EB = (NE + 255) / 256;
    const int GW = (NN * 32 + 255) / 256;

    k_init<<<NBLK, 256>>>(ei);
    k_hist<<<EB, 256>>>(ei);
    k_scan1<<<NBLK, 256>>>();
    k_scan3m<<<NBLK, 256>>>();
    k_reorder<<<EB, 256>>>(ei);
    k_gather_x<<<GW, 256>>>(x);
    k_gemm1_mma<<<GT, 256, SM_MMA_TOTAL>>>(x, Wl1, bl1, Wr1, Wl2);
    k_gather_p<<<GW, 256>>>();
    k_gemmF<<<GN, 256, SM2>>>(Wr2, bl2, out);
}